// round 16
// baseline (speedup 1.0000x reference)
#include <cuda_runtime.h>
#include <cuda_fp16.h>
#include <cstdint>
#include <math.h>

// ---------------------------------------------------------------------------
// Problem constants
// ---------------------------------------------------------------------------
#define C_TOT   2048
#define HW2     196
#define O_REAL  48
#define MAXB    64
#define M_TILE  64
#define MTILES  196            // 12544 / 64
#define KSPLIT  2
#define K_PER   (C_TOT / KSPLIT)   // 1024
#define KC      128
#define NCH_CTA (K_PER / KC)   // 8 chunks per CTA
#define NCH_ALL (C_TOT / KC)   // 16 chunks total
#define NSTEP   (K_PER / 32)   // 32 k32 steps per CTA
#define PF      3              // prefetch distance (k32 steps)

// W fp16 image: per chunk, 48 rows x 68 words (64 data + 4 pad)
#define ROWW    68
#define CHUNKW  (48 * ROWW)            // 3264 words
#define CHUNK_BYTES (CHUNKW * 4)       // 13056
#define CP_UNITS (CHUNK_BYTES / 16)    // 816

#define XST     52                     // epilogue smem row stride (words)

// Scratch
__device__ uint32_t g_wimg[(size_t)NCH_ALL * CHUNKW];                   // 209 KB
__device__ float    g_part[(size_t)KSPLIT * MTILES * M_TILE * O_REAL]; // 4.8 MB

// ---------------------------------------------------------------------------
// helpers
// ---------------------------------------------------------------------------
__device__ __forceinline__ void hmma16816(float* c, const uint32_t* a,
                                          uint32_t b0, uint32_t b1) {
    asm volatile(
        "mma.sync.aligned.m16n8k16.row.col.f32.f16.f16.f32 "
        "{%0,%1,%2,%3}, {%4,%5,%6,%7}, {%8,%9}, {%0,%1,%2,%3};"
        : "+f"(c[0]), "+f"(c[1]), "+f"(c[2]), "+f"(c[3])
        : "r"(a[0]), "r"(a[1]), "r"(a[2]), "r"(a[3]), "r"(b0), "r"(b1));
}
__device__ __forceinline__ uint32_t h2pack(float e, float o) {
    uint32_t r;
    asm("cvt.rn.f16x2.f32 %0, %1, %2;" : "=r"(r) : "f"(o), "f"(e));
    return r;
}
__device__ __forceinline__ void cp_async16(uint32_t saddr, const void* gaddr) {
    asm volatile("cp.async.cg.shared.global [%0], [%1], 16;" :: "r"(saddr), "l"(gaddr));
}
__device__ __forceinline__ uint32_t smem_u32addr(const void* p) {
    uint32_t a;
    asm("{ .reg .u64 t; cvta.to.shared.u64 t, %1; cvt.u32.u64 %0, t; }" : "=r"(a) : "l"(p));
    return a;
}
// streaming (evict-first) global load: x has zero reuse, keep L2 for W+partials
__device__ __forceinline__ float ldcs(const float* p) {
    float v;
    asm volatile("ld.global.cs.f32 %0, [%1];" : "=f"(v) : "l"(p));
    return v;
}

// ---------------------------------------------------------------------------
// Prep: W -> fp16 image. One thread per output word (16*48*64 = 49152).
// ---------------------------------------------------------------------------
__global__ void __launch_bounds__(256) wsl_prep_kernel(
    const float* __restrict__ down_w,
    const float* __restrict__ fc_w)
{
    int idx = blockIdx.x * 256 + threadIdx.x;
    if (idx >= NCH_ALL * 48 * 64) return;
    int w   = idx & 63;
    int n   = (idx >> 6) % 48;
    int ci  = idx / (48 * 64);
    int s    = w >> 3;
    int r    = w & 7;
    int c    = r >> 1;
    int half = r & 1;
    int k_local = s * 16 + half * 8 + 2 * c;

    const float* wr;
    if (n < 32)      wr = down_w + (size_t)n * C_TOT;
    else if (n < 40) wr = fc_w + (size_t)(n - 32) * (2 * C_TOT);
    else             wr = fc_w + (size_t)(n - 40) * (2 * C_TOT) + C_TOT;

    float2 f = *reinterpret_cast<const float2*>(wr + ci * KC + k_local);
    g_wimg[(size_t)ci * CHUNKW + n * ROWW + w] = h2pack(f.x, f.y);
}

// ---------------------------------------------------------------------------
// Kernel A: fp16 GEMM (R7 config, prefetch depth 3, streaming x loads).
// Grid (196, 2), 128 threads. Warp w: m rows [w*16, w*16+16), all 48 n.
// ---------------------------------------------------------------------------
__global__ void __launch_bounds__(128) wsl_mma_kernel(const float* __restrict__ x)
{
    __shared__ __align__(16) uint32_t smem[2 * CHUNKW];   // 26.1 KB
    const uint32_t sbase = smem_u32addr(smem);

    const int tid  = threadIdx.x;
    const int wid  = tid >> 5;
    const int lane = tid & 31;
    const int g    = lane >> 2;
    const int c    = lane & 3;
    const int mw   = wid * 16;
    const int tile = blockIdx.x;
    const int ks   = blockIdx.y;
    const int m_base  = tile * M_TILE;
    const int ks_base = ks * K_PER;
    const int ch0     = ks * NCH_CTA;

    const int m0 = m_base + mw + g;
    const int m1 = m0 + 8;
    const int b0r = m0 / HW2, hw0 = m0 - b0r * HW2;
    const int b1r = m1 / HW2, hw1 = m1 - b1r * HW2;
    const float* pA0 = x + ((size_t)b0r * C_TOT) * HW2 + hw0;
    const float* pA1 = x + ((size_t)b1r * C_TOT) * HW2 + hw1;

    float acc[6][4];
#pragma unroll
    for (int t = 0; t < 6; t++)
#pragma unroll
        for (int j = 0; j < 4; j++) acc[t][j] = 0.f;

    // raw A prefetch buffers, depth PF=3: [parity][8]
    float r0[PF][8], r1[PF][8];

    auto ldgA = [&](int sg, int p) {
        const int kb = ks_base + sg * 32 + 2 * c;
#pragma unroll
        for (int j = 0; j < 2; j++) {
            const size_t k = (size_t)(kb + 16 * j);
            r0[p][4 * j]     = ldcs(pA0 + k * HW2);
            r0[p][4 * j + 1] = ldcs(pA0 + (k + 1) * HW2);
            r0[p][4 * j + 2] = ldcs(pA0 + (k + 8) * HW2);
            r0[p][4 * j + 3] = ldcs(pA0 + (k + 9) * HW2);
            r1[p][4 * j]     = ldcs(pA1 + k * HW2);
            r1[p][4 * j + 1] = ldcs(pA1 + (k + 1) * HW2);
            r1[p][4 * j + 2] = ldcs(pA1 + (k + 8) * HW2);
            r1[p][4 * j + 3] = ldcs(pA1 + (k + 9) * HW2);
        }
    };

    auto issueB = [&](int ch) {
        const char* src = reinterpret_cast<const char*>(g_wimg + (size_t)(ch0 + ch) * CHUNKW);
        const uint32_t dst = sbase + (uint32_t)((ch & 1) * CHUNK_BYTES);
        for (int u = tid; u < CP_UNITS; u += 128)
            cp_async16(dst + u * 16, src + u * 16);
        asm volatile("cp.async.commit_group;" ::: "memory");
    };

    ldgA(0, 0);
    ldgA(1, 1);
    ldgA(2, 2);
    issueB(0);

    for (int ch = 0; ch < NCH_CTA; ch++) {
        if (ch + 1 < NCH_CTA) {
            issueB(ch + 1);
            asm volatile("cp.async.wait_group 1;" ::: "memory");
        } else {
            asm volatile("cp.async.wait_group 0;" ::: "memory");
        }
        __syncthreads();

        const uint32_t* buf = smem + (ch & 1) * CHUNKW;

#pragma unroll
        for (int kk = 0; kk < 4; kk++) {
            const int sg = ch * 4 + kk;
            const int p  = sg % PF;

            uint32_t af[2][4];
#pragma unroll
            for (int j = 0; j < 2; j++) {
                af[j][0] = h2pack(r0[p][4 * j],     r0[p][4 * j + 1]);
                af[j][1] = h2pack(r1[p][4 * j],     r1[p][4 * j + 1]);
                af[j][2] = h2pack(r0[p][4 * j + 2], r0[p][4 * j + 3]);
                af[j][3] = h2pack(r1[p][4 * j + 2], r1[p][4 * j + 3]);
            }

            if (sg + PF < NSTEP) ldgA(sg + PF, p);

#pragma unroll
            for (int j = 0; j < 2; j++) {
                const int s = kk * 2 + j;
#pragma unroll
                for (int t = 0; t < 6; t++) {
                    const uint2 bw = *reinterpret_cast<const uint2*>(
                        buf + (t * 8 + g) * ROWW + s * 8 + 2 * c);
                    hmma16816(acc[t], af[j], bw.x, bw.y);
                }
            }
        }
        __syncthreads();
    }

    // ---- epilogue: write partials (R7 pattern) ----
    {
        float* base0 = g_part + ((size_t)(ks * MAXB) * MTILES) * 0   // (silence)
                     + ((size_t)ks * MTILES + 0) * 0;                // placeholder no-op
        (void)base0;
        float* b0p = g_part + ((size_t)(ks * MAXB + b0r) * O_REAL) * HW2 + hw0;
        float* b1p = g_part + ((size_t)(ks * MAXB + b1r) * O_REAL) * HW2 + hw1;
#pragma unroll
        for (int t = 0; t < 6; t++) {
            const int n0 = t * 8 + 2 * c;
            b0p[(size_t)n0 * HW2]       = acc[t][0];
            b0p[(size_t)(n0 + 1) * HW2] = acc[t][1];
            b1p[(size_t)n0 * HW2]       = acc[t][2];
            b1p[(size_t)(n0 + 1) * HW2] = acc[t][3];
        }
    }
}

// ---------------------------------------------------------------------------
// Kernel B: per-batch epilogue, 1024 threads (R7's verified kernel).
// Partials layout here: [ks][b][48][196].
// ---------------------------------------------------------------------------
__global__ void __launch_bounds__(1024) wsl_final_kernel(
    const float* __restrict__ down_b,
    const float* __restrict__ fc_b,
    float* __restrict__ out,
    int B)
{
    __shared__ float xc[O_REAL * HW2];    // 9408 floats
    __shared__ float gmp[32];
    __shared__ float xout[8];
    __shared__ float red[16 * 32];
    __shared__ float psum[16];

    const int b = blockIdx.x;
    const int tid = threadIdx.x;
    const int w = tid >> 5, lane = tid & 31;

    // Sum the two K-split partials (+ bias), vectorized (196 % 4 == 0).
    {
        const float4* p0 = reinterpret_cast<const float4*>(g_part + ((size_t)b * O_REAL) * HW2);
        const float4* p1 = reinterpret_cast<const float4*>(g_part + ((size_t)(MAXB + b) * O_REAL) * HW2);
        float4* dst = reinterpret_cast<float4*>(xc);
        for (int i = tid; i < (O_REAL * HW2) / 4; i += 1024) {
            float4 a = __ldg(p0 + i);
            float4 c = __ldg(p1 + i);
            int o = i / 49;
            float bias = (o < 32) ? down_b[o] : 0.f;
            dst[i] = make_float4(a.x + c.x + bias, a.y + c.y + bias,
                                 a.z + c.z + bias, a.w + c.w + bias);
        }
    }
    __syncthreads();

    // GMP: warp w (w<32) handles map o=w.
    {
        float m1 = -INFINITY;
        for (int h = lane; h < HW2; h += 32)
            m1 = fmaxf(m1, xc[w * HW2 + h]);
#pragma unroll
        for (int off = 16; off > 0; off >>= 1)
            m1 = fmaxf(m1, __shfl_down_sync(0xffffffffu, m1, off));
        if (lane == 0) gmp[w] = m1;
    }
    __syncthreads();

    if (tid == 0) {
        float sc[8];
        float mx = -INFINITY;
        for (int j = 0; j < 8; j++) {
            sc[j] = 0.25f * (gmp[4 * j] + gmp[4 * j + 1] + gmp[4 * j + 2] + gmp[4 * j + 3]);
            mx = fmaxf(mx, sc[j]);
        }
        float se = 0.f;
        for (int j = 0; j < 8; j++) se += expf(sc[j] - mx);
        float lse = mx + logf(se);
        for (int j = 0; j < 8; j++) {
            float v = sc[j] - lse;
            xout[j] = v;
            out[(size_t)b * 8 + j] = v;
        }
    }
    __syncthreads();

    float v[16];
    if (tid < HW2) {
        float sal = 0.f;
#pragma unroll
        for (int j = 0; j < 8; j++) {
            float cls = xc[(4 * j) * HW2 + tid] + xc[(4 * j + 1) * HW2 + tid] +
                        xc[(4 * j + 2) * HW2 + tid] + xc[(4 * j + 3) * HW2 + tid];
            sal += xout[j] * cls;
        }
        sal *= (1.f / 32.f);
#pragma unroll
        for (int j = 0; j < 8; j++) {
            v[j]     = xc[(32 + j) * HW2 + tid];
            v[8 + j] = sal * xc[(40 + j) * HW2 + tid];
        }
    } else {
#pragma unroll
        for (int k = 0; k < 16; k++) v[k] = 0.f;
    }
#pragma unroll
    for (int off = 16; off > 0; off >>= 1) {
#pragma unroll
        for (int k = 0; k < 16; k++)
            v[k] += __shfl_down_sync(0xffffffffu, v[k], off);
    }
    if (lane == 0) {
#pragma unroll
        for (int k = 0; k < 16; k++) red[k * 32 + w] = v[k];
    }
    __syncthreads();
    if (tid < 16) {
        float s = 0.f;
#pragma unroll
        for (int ww = 0; ww < 32; ww++) s += red[tid * 32 + ww];
        psum[tid] = s;
    }
    __syncthreads();

    if (tid == 0) {
        float lg[8];
        float mx = -INFINITY;
        for (int j = 0; j < 8; j++) {
            lg[j] = (psum[j] + psum[8 + j]) * (1.f / 196.f) + fc_b[j];
            mx = fmaxf(mx, lg[j]);
        }
        float se = 0.f;
        for (int j = 0; j < 8; j++) se += expf(lg[j] - mx);
        float lse = mx + logf(se);
        for (int j = 0; j < 8; j++)
            out[(size_t)B * 8 + (size_t)b * 8 + j] = lg[j] - lse;
    }
}

// ---------------------------------------------------------------------------
extern "C" void kernel_launch(void* const* d_in, const int* in_sizes, int n_in,
                              void* d_out, int out_size)
{
    const float* x      = (const float*)d_in[0];
    const float* down_w = (const float*)d_in[1];
    const float* down_b = (const float*)d_in[2];
    const float* fc_w   = (const float*)d_in[3];
    const float* fc_b   = (const float*)d_in[4];
    float* out = (float*)d_out;

    int B = in_sizes[0] / (C_TOT * HW2);   // 64

    wsl_prep_kernel<<<192, 256>>>(down_w, fc_w);
    dim3 gridA(MTILES, KSPLIT);
    wsl_mma_kernel<<<gridA, 128>>>(x);
    wsl_final_kernel<<<B, 1024>>>(down_b, fc_b, out, B);
}

// round 17
// speedup vs baseline: 2.2993x; 2.2993x over previous
#include <cuda_runtime.h>
#include <cuda_fp16.h>
#include <cstdint>
#include <math.h>

// ---------------------------------------------------------------------------
// Problem constants
// ---------------------------------------------------------------------------
#define C_TOT   2048
#define HW2     196
#define O_REAL  48
#define MAXB    64
#define M_TILE  64
#define MTILES  196            // 12544 / 64
#define KSPLIT  2
#define K_PER   (C_TOT / KSPLIT)   // 1024
#define KC      128            // k per smem chunk
#define NCH     (K_PER / KC)   // 8 chunks per CTA
#define NSTEP   (K_PER / 32)   // 32 k32 steps per CTA

// W fp16 image: per chunk (16 total), 48 rows x 72 words (64 data + 8 pad)
// Row word layout: k16 step s (8 per chunk) x 8 words:
//   word s*8 + 2c + half : fp16x2( k = 16s + 8*half + 2c, +1 )
#define ROWW    72
#define CHUNKW  (48 * ROWW)            // 3456 words
#define CHUNK_BYTES (CHUNKW * 4)       // 13824
#define CP_UNITS (CHUNK_BYTES / 16)    // 864

// Scratch
__device__ float    g_part[(size_t)KSPLIT * MAXB * O_REAL * HW2];   // 4.8 MB
__device__ uint32_t g_wimg[(size_t)16 * CHUNKW];                    // 221 KB

// ---------------------------------------------------------------------------
// helpers
// ---------------------------------------------------------------------------
__device__ __forceinline__ void hmma16816(float* c, const uint32_t* a,
                                          uint32_t b0, uint32_t b1) {
    asm volatile(
        "mma.sync.aligned.m16n8k16.row.col.f32.f16.f16.f32 "
        "{%0,%1,%2,%3}, {%4,%5,%6,%7}, {%8,%9}, {%0,%1,%2,%3};"
        : "+f"(c[0]), "+f"(c[1]), "+f"(c[2]), "+f"(c[3])
        : "r"(a[0]), "r"(a[1]), "r"(a[2]), "r"(a[3]), "r"(b0), "r"(b1));
}
// pack two fp16 (rn): lo half = e, hi half = o
__device__ __forceinline__ uint32_t h2pack(float e, float o) {
    uint32_t r;
    asm("cvt.rn.f16x2.f32 %0, %1, %2;" : "=r"(r) : "f"(o), "f"(e));
    return r;
}
__device__ __forceinline__ uint32_t smem_u32addr(const void* p) {
    uint32_t a;
    asm("{ .reg .u64 t; cvta.to.shared.u64 t, %1; cvt.u32.u64 %0, t; }" : "=r"(a) : "l"(p));
    return a;
}
__device__ __forceinline__ void cp_async16(uint32_t saddr, const void* gaddr) {
    asm volatile("cp.async.cg.shared.global [%0], [%1], 16;" :: "r"(saddr), "l"(gaddr));
}
// streaming (evict-first) global load: x has zero reuse; keep L2 for W+partials
__device__ __forceinline__ float ldcs(const float* p) {
    float v;
    asm volatile("ld.global.cs.f32 %0, [%1];" : "=f"(v) : "l"(p));
    return v;
}

// ---------------------------------------------------------------------------
// Prep: W -> fp16 image. One thread per output word (16*48*64 = 49152).
// ---------------------------------------------------------------------------
__global__ void __launch_bounds__(256) wsl_prep_kernel(
    const float* __restrict__ down_w,
    const float* __restrict__ fc_w)
{
    int idx = blockIdx.x * 256 + threadIdx.x;
    if (idx >= 16 * 48 * 64) return;
    int w   = idx & 63;
    int n   = (idx >> 6) % 48;
    int ci  = idx / (48 * 64);
    int s    = w >> 3;
    int r    = w & 7;
    int c    = r >> 1;
    int half = r & 1;
    int k_local = s * 16 + half * 8 + 2 * c;

    const float* wr;
    if (n < 32)      wr = down_w + (size_t)n * C_TOT;
    else if (n < 40) wr = fc_w + (size_t)(n - 32) * (2 * C_TOT);
    else             wr = fc_w + (size_t)(n - 40) * (2 * C_TOT) + C_TOT;

    float2 f = *reinterpret_cast<const float2*>(wr + ci * KC + k_local);
    g_wimg[(size_t)ci * CHUNKW + n * ROWW + w] = h2pack(f.x, f.y);
}

// ---------------------------------------------------------------------------
// Kernel A: fp16 GEMM (1 HMMA per k16 per n-tile). Grid (196, 2), 128 thr.
// Identical to R7 except x loads use ld.global.cs.
// ---------------------------------------------------------------------------
__global__ void __launch_bounds__(128) wsl_mma_kernel(const float* __restrict__ x)
{
    __shared__ __align__(16) uint32_t smem[2 * CHUNKW];   // 27.6 KB
    const uint32_t sbase = smem_u32addr(smem);

    const int tid  = threadIdx.x;
    const int wid  = tid >> 5;
    const int lane = tid & 31;
    const int g    = lane >> 2;
    const int c    = lane & 3;
    const int m_base  = blockIdx.x * M_TILE;
    const int ks      = blockIdx.y;
    const int ks_base = ks * K_PER;
    const int ch0     = ks * NCH;

    const int m0 = m_base + wid * 16 + g;
    const int m1 = m0 + 8;
    const int b0r = m0 / HW2, hw0 = m0 - b0r * HW2;
    const int b1r = m1 / HW2, hw1 = m1 - b1r * HW2;
    const float* pA0 = x + ((size_t)b0r * C_TOT) * HW2 + hw0;
    const float* pA1 = x + ((size_t)b1r * C_TOT) * HW2 + hw1;

    float acc[6][4];
#pragma unroll
    for (int t = 0; t < 6; t++)
#pragma unroll
        for (int j = 0; j < 4; j++) acc[t][j] = 0.f;

    // raw A prefetch (distance 2 k32-steps): [parity][4j+i]
    float r0[2][8], r1[2][8];

    auto ldgA = [&](int sg, int p) {
        const int kb = ks_base + sg * 32 + 2 * c;
#pragma unroll
        for (int j = 0; j < 2; j++) {
            const size_t k = (size_t)(kb + 16 * j);
            r0[p][4 * j]     = ldcs(pA0 + k * HW2);
            r0[p][4 * j + 1] = ldcs(pA0 + (k + 1) * HW2);
            r0[p][4 * j + 2] = ldcs(pA0 + (k + 8) * HW2);
            r0[p][4 * j + 3] = ldcs(pA0 + (k + 9) * HW2);
            r1[p][4 * j]     = ldcs(pA1 + k * HW2);
            r1[p][4 * j + 1] = ldcs(pA1 + (k + 1) * HW2);
            r1[p][4 * j + 2] = ldcs(pA1 + (k + 8) * HW2);
            r1[p][4 * j + 3] = ldcs(pA1 + (k + 9) * HW2);
        }
    };

    auto issueB = [&](int ch) {
        const char* src = reinterpret_cast<const char*>(g_wimg + (size_t)(ch0 + ch) * CHUNKW);
        const uint32_t dst = sbase + (uint32_t)((ch & 1) * CHUNK_BYTES);
        for (int u = tid; u < CP_UNITS; u += 128)
            cp_async16(dst + u * 16, src + u * 16);
        asm volatile("cp.async.commit_group;" ::: "memory");
    };

    ldgA(0, 0);
    ldgA(1, 1);
    issueB(0);

    for (int ch = 0; ch < NCH; ch++) {
        if (ch + 1 < NCH) {
            issueB(ch + 1);
            asm volatile("cp.async.wait_group 1;" ::: "memory");
        } else {
            asm volatile("cp.async.wait_group 0;" ::: "memory");
        }
        __syncthreads();

        const uint32_t* buf = smem + (ch & 1) * CHUNKW;

#pragma unroll
        for (int kk = 0; kk < 4; kk++) {
            const int sg = ch * 4 + kk;
            const int p  = sg & 1;

            // convert raw A -> fp16 frags for the two k16 steps of this k32
            uint32_t af[2][4];
#pragma unroll
            for (int j = 0; j < 2; j++) {
                af[j][0] = h2pack(r0[p][4 * j],     r0[p][4 * j + 1]); // m0, k lo
                af[j][1] = h2pack(r1[p][4 * j],     r1[p][4 * j + 1]); // m1, k lo
                af[j][2] = h2pack(r0[p][4 * j + 2], r0[p][4 * j + 3]); // m0, k hi
                af[j][3] = h2pack(r1[p][4 * j + 2], r1[p][4 * j + 3]); // m1, k hi
            }

            if (sg + 2 < NSTEP) ldgA(sg + 2, p);

#pragma unroll
            for (int j = 0; j < 2; j++) {
                const int s = kk * 2 + j;    // k16 step within chunk
#pragma unroll
                for (int t = 0; t < 6; t++) {
                    const uint2 bw = *reinterpret_cast<const uint2*>(
                        buf + (t * 8 + g) * ROWW + s * 8 + 2 * c);
                    hmma16816(acc[t], af[j], bw.x, bw.y);
                }
            }
        }
        __syncthreads();
    }

    // epilogue: write partials
    {
        float* base0 = g_part + ((size_t)(ks * MAXB + b0r) * O_REAL) * HW2 + hw0;
        float* base1 = g_part + ((size_t)(ks * MAXB + b1r) * O_REAL) * HW2 + hw1;
#pragma unroll
        for (int t = 0; t < 6; t++) {
            const int n0 = t * 8 + 2 * c;
            base0[(size_t)n0 * HW2]       = acc[t][0];
            base0[(size_t)(n0 + 1) * HW2] = acc[t][1];
            base1[(size_t)n0 * HW2]       = acc[t][2];
            base1[(size_t)(n0 + 1) * HW2] = acc[t][3];
        }
    }
}

// ---------------------------------------------------------------------------
// Kernel B: per-batch epilogue, 1024 threads (R7's verified kernel).
// ---------------------------------------------------------------------------
__global__ void __launch_bounds__(1024) wsl_final_kernel(
    const float* __restrict__ down_b,
    const float* __restrict__ fc_b,
    float* __restrict__ out,
    int B)
{
    __shared__ float xc[O_REAL * HW2];    // 9408 floats
    __shared__ float gmp[32];
    __shared__ float xout[8];
    __shared__ float red[16 * 32];
    __shared__ float psum[16];

    const int b = blockIdx.x;
    const int tid = threadIdx.x;
    const int w = tid >> 5, lane = tid & 31;

    // Sum the two K-split partials (+ bias), vectorized (196 % 4 == 0).
    {
        const float4* p0 = reinterpret_cast<const float4*>(g_part + ((size_t)b * O_REAL) * HW2);
        const float4* p1 = reinterpret_cast<const float4*>(g_part + ((size_t)(MAXB + b) * O_REAL) * HW2);
        float4* dst = reinterpret_cast<float4*>(xc);
        for (int i = tid; i < (O_REAL * HW2) / 4; i += 1024) {
            float4 a = __ldg(p0 + i);
            float4 c = __ldg(p1 + i);
            int o = i / 49;
            float bias = (o < 32) ? down_b[o] : 0.f;
            dst[i] = make_float4(a.x + c.x + bias, a.y + c.y + bias,
                                 a.z + c.z + bias, a.w + c.w + bias);
        }
    }
    __syncthreads();

    // GMP: warp w (w<32) handles map o=w.
    {
        float m1 = -INFINITY;
        for (int h = lane; h < HW2; h += 32)
            m1 = fmaxf(m1, xc[w * HW2 + h]);
#pragma unroll
        for (int off = 16; off > 0; off >>= 1)
            m1 = fmaxf(m1, __shfl_down_sync(0xffffffffu, m1, off));
        if (lane == 0) gmp[w] = m1;
    }
    __syncthreads();

    if (tid == 0) {
        float sc[8];
        float mx = -INFINITY;
        for (int j = 0; j < 8; j++) {
            sc[j] = 0.25f * (gmp[4 * j] + gmp[4 * j + 1] + gmp[4 * j + 2] + gmp[4 * j + 3]);
            mx = fmaxf(mx, sc[j]);
        }
        float se = 0.f;
        for (int j = 0; j < 8; j++) se += expf(sc[j] - mx);
        float lse = mx + logf(se);
        for (int j = 0; j < 8; j++) {
            float v = sc[j] - lse;
            xout[j] = v;
            out[(size_t)b * 8 + j] = v;
        }
    }
    __syncthreads();

    float v[16];
    if (tid < HW2) {
        float sal = 0.f;
#pragma unroll
        for (int j = 0; j < 8; j++) {
            float cls = xc[(4 * j) * HW2 + tid] + xc[(4 * j + 1) * HW2 + tid] +
                        xc[(4 * j + 2) * HW2 + tid] + xc[(4 * j + 3) * HW2 + tid];
            sal += xout[j] * cls;
        }
        sal *= (1.f / 32.f);
#pragma unroll
        for (int j = 0; j < 8; j++) {
            v[j]     = xc[(32 + j) * HW2 + tid];
            v[8 + j] = sal * xc[(40 + j) * HW2 + tid];
        }
    } else {
#pragma unroll
        for (int k = 0; k < 16; k++) v[k] = 0.f;
    }
#pragma unroll
    for (int off = 16; off > 0; off >>= 1) {
#pragma unroll
        for (int k = 0; k < 16; k++)
            v[k] += __shfl_down_sync(0xffffffffu, v[k], off);
    }
    if (lane == 0) {
#pragma unroll
        for (int k = 0; k < 16; k++) red[k * 32 + w] = v[k];
    }
    __syncthreads();
    if (tid < 16) {
        float s = 0.f;
#pragma unroll
        for (int ww = 0; ww < 32; ww++) s += red[tid * 32 + ww];
        psum[tid] = s;
    }
    __syncthreads();

    if (tid == 0) {
        float lg[8];
        float mx = -INFINITY;
        for (int j = 0; j < 8; j++) {
            lg[j] = (psum[j] + psum[8 + j]) * (1.f / 196.f) + fc_b[j];
            mx = fmaxf(mx, lg[j]);
        }
        float se = 0.f;
        for (int j = 0; j < 8; j++) se += expf(lg[j] - mx);
        float lse = mx + logf(se);
        for (int j = 0; j < 8; j++)
            out[(size_t)B * 8 + (size_t)b * 8 + j] = lg[j] - lse;
    }
}

// ---------------------------------------------------------------------------
extern "C" void kernel_launch(void* const* d_in, const int* in_sizes, int n_in,
                              void* d_out, int out_size)
{
    const float* x      = (const float*)d_in[0];
    const float* down_w = (const float*)d_in[1];
    const float* down_b = (const float*)d_in[2];
    const float* fc_w   = (const float*)d_in[3];
    const float* fc_b   = (const float*)d_in[4];
    float* out = (float*)d_out;

    int B = in_sizes[0] / (C_TOT * HW2);   // 64

    wsl_prep_kernel<<<192, 256>>>(down_w, fc_w);
    dim3 gridA(MTILES, KSPLIT);
    wsl_mma_kernel<<<gridA, 128>>>(x);
    wsl_final_kernel<<<B, 1024>>>(down_b, fc_b, out, B);
}